// round 1
// baseline (speedup 1.0000x reference)
#include <cuda_runtime.h>
#include <math.h>
#include <float.h>

#define Nn 50000
#define Ee 600000
#define Hh 128
#define Gg 512
#define Mm (Ee + Nn)
#define PI_F 3.14159265358979323846f

// ---------------- scratch (device globals: no allocation allowed) ----------------
static __device__ float g_loop[(size_t)Nn * Hh];
static __device__ float g_deg[Nn];
static __device__ float g_xl[(size_t)Nn * Hh];
static __device__ float g_xr[(size_t)Nn * Hh];
static __device__ float g_eW[(size_t)Mm * Hh];   // 333 MB
static __device__ float g_e[Mm];
static __device__ float g_emax[Nn];
static __device__ float g_esum[Nn];
static __device__ float g_agg[(size_t)Nn * Hh];
static __device__ float g_h[(size_t)Nn * Hh];
static __device__ float g_gate[(size_t)Nn * Hh];
static __device__ float g_tmp[(size_t)Nn * Hh];
static __device__ float g_bnsum[Hh];
static __device__ float g_bnsq[Hh];
static __device__ float g_mu[Hh];
static __device__ float g_inv[Hh];
static __device__ float g_gmax[Gg * Hh];
static __device__ float g_den[Gg * Hh];
static __device__ float g_num[Gg * Hh];
static __device__ float g_pooled[Gg * Hh];

// ---------------- helpers ----------------
__device__ __forceinline__ void atomicMaxF(float* addr, float v) {
    int* ai = reinterpret_cast<int*>(addr);
    int old = *ai;
    while (__int_as_float(old) < v) {
        int assumed = old;
        old = atomicCAS(ai, assumed, __float_as_int(v));
        if (old == assumed) break;
    }
}

__global__ void k_fill(float* __restrict__ p, float v, int n) {
    int i = blockIdx.x * blockDim.x + threadIdx.x;
    if (i < n) p[i] = v;
}

// ---------------- self-loop edge_attr mean ----------------
__global__ void k_scatter_loop(const int* __restrict__ ei, const float* __restrict__ eattr) {
    int t = blockIdx.x * blockDim.x + threadIdx.x;
    int w = t >> 5, lane = t & 31;
    if (w >= Ee) return;
    int d = ei[Ee + w];
    float4 a = reinterpret_cast<const float4*>(eattr)[(size_t)w * (Hh / 4) + lane];
    float* p = g_loop + (size_t)d * Hh + lane * 4;
    atomicAdd(p + 0, a.x); atomicAdd(p + 1, a.y);
    atomicAdd(p + 2, a.z); atomicAdd(p + 3, a.w);
    if (lane == 0) atomicAdd(&g_deg[d], 1.0f);
}

__global__ void k_div_loop() {
    int i = blockIdx.x * blockDim.x + threadIdx.x;
    if (i >= Nn * Hh) return;
    g_loop[i] = g_loop[i] / fmaxf(g_deg[i >> 7], 1.0f);
}

// ---------------- SGEMM: C[rows,128] = A[rows,128] @ B[128,128] (+bias, act) ----------------
// BM=128, BN=128, BK=32, 256 threads, 8x8 micro-tile per thread.
template <int ACT>
__global__ void k_gemm(const float* __restrict__ A, const float* __restrict__ B,
                       const float* __restrict__ bias, float* __restrict__ C, int rows) {
    __shared__ float As[32][132];  // transposed A tile (pad 4 -> conflict-free, 16B aligned)
    __shared__ float Bs[32][128];
    const int tid  = threadIdx.x;
    const int row0 = blockIdx.x * 128;
    const int tcol = tid & 15;
    const int trow = tid >> 4;

    float acc[8][8];
#pragma unroll
    for (int i = 0; i < 8; i++)
#pragma unroll
        for (int j = 0; j < 8; j++) acc[i][j] = 0.f;

    for (int kk = 0; kk < Hh; kk += 32) {
#pragma unroll
        for (int i = 0; i < 4; i++) {
            int t4 = tid + i * 256;
            int r  = t4 >> 3;
            int c4 = (t4 & 7) << 2;
            int row = row0 + r;
            float4 v = make_float4(0.f, 0.f, 0.f, 0.f);
            if (row < rows)
                v = *reinterpret_cast<const float4*>(A + (size_t)row * Hh + kk + c4);
            As[c4 + 0][r] = v.x; As[c4 + 1][r] = v.y;
            As[c4 + 2][r] = v.z; As[c4 + 3][r] = v.w;
        }
#pragma unroll
        for (int i = 0; i < 4; i++) {
            int t4 = tid + i * 256;
            int k  = t4 >> 5;
            int c  = (t4 & 31) << 2;
            *reinterpret_cast<float4*>(&Bs[k][c]) =
                *reinterpret_cast<const float4*>(B + (size_t)(kk + k) * Hh + c);
        }
        __syncthreads();
#pragma unroll
        for (int k = 0; k < 32; k++) {
            float a[8], b[8];
            *reinterpret_cast<float4*>(&a[0]) = *reinterpret_cast<float4*>(&As[k][trow * 8]);
            *reinterpret_cast<float4*>(&a[4]) = *reinterpret_cast<float4*>(&As[k][trow * 8 + 4]);
            *reinterpret_cast<float4*>(&b[0]) = *reinterpret_cast<float4*>(&Bs[k][tcol * 8]);
            *reinterpret_cast<float4*>(&b[4]) = *reinterpret_cast<float4*>(&Bs[k][tcol * 8 + 4]);
#pragma unroll
            for (int i = 0; i < 8; i++)
#pragma unroll
                for (int j = 0; j < 8; j++) acc[i][j] = fmaf(a[i], b[j], acc[i][j]);
        }
        __syncthreads();
    }

#pragma unroll
    for (int i = 0; i < 8; i++) {
        int row = row0 + trow * 8 + i;
        if (row >= rows) return;
        float* crow = C + (size_t)row * Hh + tcol * 8;
#pragma unroll
        for (int j = 0; j < 8; j++) {
            float v = acc[i][j];
            if (bias) v += bias[tcol * 8 + j];
            if (ACT == 1) v = tanhf(v);
            if (ACT == 2) v = tanhf(v) * PI_F;
            crow[j] = v;
        }
    }
}

// ---------------- GATv2 edge kernels (warp per edge; self loops appended) ----------------
__global__ void k_edge_score(const int* __restrict__ ei, const float* __restrict__ att) {
    int t = blockIdx.x * blockDim.x + threadIdx.x;
    int w = t >> 5, lane = t & 31;
    if (w >= Mm) return;
    int s, d;
    if (w < Ee) { s = ei[w]; d = ei[Ee + w]; } else { s = w - Ee; d = s; }
    float4 ww = reinterpret_cast<const float4*>(g_eW)[(size_t)w * 32 + lane];
    float4 a  = reinterpret_cast<const float4*>(g_xl)[s * 32 + lane];
    float4 b  = reinterpret_cast<const float4*>(g_xr)[d * 32 + lane];
    float4 at = reinterpret_cast<const float4*>(att)[lane];
    float m, sum = 0.f;
    m = ww.x + a.x + b.x; m = m > 0.f ? m : 0.2f * m; sum += m * at.x;
    m = ww.y + a.y + b.y; m = m > 0.f ? m : 0.2f * m; sum += m * at.y;
    m = ww.z + a.z + b.z; m = m > 0.f ? m : 0.2f * m; sum += m * at.z;
    m = ww.w + a.w + b.w; m = m > 0.f ? m : 0.2f * m; sum += m * at.w;
#pragma unroll
    for (int o = 16; o > 0; o >>= 1) sum += __shfl_xor_sync(0xffffffffu, sum, o);
    if (lane == 0) g_e[w] = sum;
}

__global__ void k_edge_max(const int* __restrict__ ei) {
    int w = blockIdx.x * blockDim.x + threadIdx.x;
    if (w >= Mm) return;
    int d = (w < Ee) ? ei[Ee + w] : (w - Ee);
    atomicMaxF(&g_emax[d], g_e[w]);
}

__global__ void k_edge_expsum(const int* __restrict__ ei) {
    int w = blockIdx.x * blockDim.x + threadIdx.x;
    if (w >= Mm) return;
    int d = (w < Ee) ? ei[Ee + w] : (w - Ee);
    float ex = expf(g_e[w] - g_emax[d]);
    g_e[w] = ex;
    atomicAdd(&g_esum[d], ex);
}

__global__ void k_edge_agg(const int* __restrict__ ei) {
    int t = blockIdx.x * blockDim.x + threadIdx.x;
    int w = t >> 5, lane = t & 31;
    if (w >= Mm) return;
    int s, d;
    if (w < Ee) { s = ei[w]; d = ei[Ee + w]; } else { s = w - Ee; d = s; }
    float alpha = g_e[w] / g_esum[d];
    float4 a = reinterpret_cast<const float4*>(g_xl)[s * 32 + lane];
    float* p = g_agg + (size_t)d * Hh + lane * 4;
    atomicAdd(p + 0, alpha * a.x); atomicAdd(p + 1, alpha * a.y);
    atomicAdd(p + 2, alpha * a.z); atomicAdd(p + 3, alpha * a.w);
}

// ---------------- batchnorm (population stats) + tanh ----------------
__global__ void k_bn_stats(const float* __restrict__ cb) {
    int j  = threadIdx.x;  // 128
    int r0 = blockIdx.x * 128;
    int r1 = min(r0 + 128, Nn);
    float cbj = cb[j];
    float s = 0.f, q = 0.f;
    for (int r = r0; r < r1; r++) {
        float v = g_agg[(size_t)r * Hh + j] + cbj;
        s += v; q += v * v;
    }
    atomicAdd(&g_bnsum[j], s);
    atomicAdd(&g_bnsq[j], q);
}

__global__ void k_bn_final() {
    int j = threadIdx.x;
    float mu  = g_bnsum[j] / (float)Nn;
    float var = g_bnsq[j] / (float)Nn - mu * mu;
    g_mu[j]  = mu;
    g_inv[j] = rsqrtf(var + 1e-5f);
}

__global__ void k_bn_apply(const float* __restrict__ cb, const float* __restrict__ gam,
                           const float* __restrict__ bet) {
    int i = blockIdx.x * blockDim.x + threadIdx.x;
    if (i >= Nn * Hh) return;
    int j = i & 127;
    float v = g_agg[i] + cb[j];
    v = (v - g_mu[j]) * g_inv[j] * gam[j] + bet[j];
    g_h[i] = tanhf(v);
}

// ---------------- attentional pooling ----------------
__global__ void k_pool_max(const int* __restrict__ batch) {
    int i = blockIdx.x * blockDim.x + threadIdx.x;
    if (i >= Nn * Hh) return;
    int n = i >> 7, j = i & 127;
    atomicMaxF(&g_gmax[batch[n] * Hh + j], g_gate[i]);
}

__global__ void k_pool_sum(const int* __restrict__ batch) {
    int i = blockIdx.x * blockDim.x + threadIdx.x;
    if (i >= Nn * Hh) return;
    int n = i >> 7, j = i & 127;
    int gi = batch[n] * Hh + j;
    float ex = expf(g_gate[i] - g_gmax[gi]);
    atomicAdd(&g_den[gi], ex);
    atomicAdd(&g_num[gi], ex * g_h[i]);
}

__global__ void k_pool_div() {
    int i = blockIdx.x * blockDim.x + threadIdx.x;
    if (i >= Gg * Hh) return;
    g_pooled[i] = g_num[i] / fmaxf(g_den[i], 1e-16f);
}

// ---------------- launch ----------------
static inline int cdiv(long a, long b) { return (int)((a + b - 1) / b); }

extern "C" void kernel_launch(void* const* d_in, const int* in_sizes, int n_in,
                              void* d_out, int out_size) {
    const float* x     = (const float*)d_in[0];
    const int*   ei    = (const int*)d_in[1];
    const float* eattr = (const float*)d_in[2];
    const int*   batch = (const int*)d_in[3];
    const float* Wl[2]  = {(const float*)d_in[4],  (const float*)d_in[11]};
    const float* bl[2]  = {(const float*)d_in[5],  (const float*)d_in[12]};
    const float* Wr[2]  = {(const float*)d_in[6],  (const float*)d_in[13]};
    const float* br[2]  = {(const float*)d_in[7],  (const float*)d_in[14]};
    const float* We[2]  = {(const float*)d_in[8],  (const float*)d_in[15]};
    const float* att[2] = {(const float*)d_in[9],  (const float*)d_in[16]};
    const float* cb[2]  = {(const float*)d_in[10], (const float*)d_in[17]};
    const float* gm[2]  = {(const float*)d_in[18], (const float*)d_in[20]};
    const float* bt[2]  = {(const float*)d_in[19], (const float*)d_in[21]};
    const float* A1 = (const float*)d_in[22]; const float* a1 = (const float*)d_in[23];
    const float* A2 = (const float*)d_in[24]; const float* a2 = (const float*)d_in[25];
    const float* Wf = (const float*)d_in[26]; const float* bf = (const float*)d_in[27];
    float* out = (float*)d_out;

    float *p_loop, *p_deg, *p_xl, *p_xr, *p_eW, *p_e, *p_emax, *p_esum, *p_agg, *p_h,
          *p_gate, *p_tmp, *p_bnsum, *p_bnsq, *p_gmax, *p_den, *p_num, *p_pooled;
    cudaGetSymbolAddress((void**)&p_loop, g_loop);
    cudaGetSymbolAddress((void**)&p_deg, g_deg);
    cudaGetSymbolAddress((void**)&p_xl, g_xl);
    cudaGetSymbolAddress((void**)&p_xr, g_xr);
    cudaGetSymbolAddress((void**)&p_eW, g_eW);
    cudaGetSymbolAddress((void**)&p_e, g_e);
    cudaGetSymbolAddress((void**)&p_emax, g_emax);
    cudaGetSymbolAddress((void**)&p_esum, g_esum);
    cudaGetSymbolAddress((void**)&p_agg, g_agg);
    cudaGetSymbolAddress((void**)&p_h, g_h);
    cudaGetSymbolAddress((void**)&p_gate, g_gate);
    cudaGetSymbolAddress((void**)&p_tmp, g_tmp);
    cudaGetSymbolAddress((void**)&p_bnsum, g_bnsum);
    cudaGetSymbolAddress((void**)&p_bnsq, g_bnsq);
    cudaGetSymbolAddress((void**)&p_gmax, g_gmax);
    cudaGetSymbolAddress((void**)&p_den, g_den);
    cudaGetSymbolAddress((void**)&p_num, g_num);
    cudaGetSymbolAddress((void**)&p_pooled, g_pooled);

    const int NH = Nn * Hh;
    const int gemmN = cdiv(Nn, 128), gemmE = cdiv(Ee, 128), gemmG = cdiv(Gg, 128);

    // self-loop edge_attr = per-dst mean
    k_fill<<<cdiv(NH, 256), 256>>>(p_loop, 0.f, NH);
    k_fill<<<cdiv(Nn, 256), 256>>>(p_deg, 0.f, Nn);
    k_scatter_loop<<<cdiv((long)Ee * 32, 256), 256>>>(ei, eattr);
    k_div_loop<<<cdiv(NH, 256), 256>>>();

    for (int l = 0; l < 2; l++) {
        const float* xin = (l == 0) ? x : p_h;
        k_gemm<0><<<gemmN, 256>>>(xin, Wl[l], bl[l], p_xl, Nn);
        k_gemm<0><<<gemmN, 256>>>(xin, Wr[l], br[l], p_xr, Nn);
        k_gemm<0><<<gemmE, 256>>>(eattr, We[l], nullptr, p_eW, Ee);
        k_gemm<0><<<gemmN, 256>>>(p_loop, We[l], nullptr, p_eW + (size_t)Ee * Hh, Nn);

        k_fill<<<cdiv(Nn, 256), 256>>>(p_emax, -FLT_MAX, Nn);
        k_fill<<<cdiv(Nn, 256), 256>>>(p_esum, 0.f, Nn);
        k_fill<<<cdiv(NH, 256), 256>>>(p_agg, 0.f, NH);

        k_edge_score<<<cdiv((long)Mm * 32, 256), 256>>>(ei, att[l]);
        k_edge_max<<<cdiv(Mm, 256), 256>>>(ei);
        k_edge_expsum<<<cdiv(Mm, 256), 256>>>(ei);
        k_edge_agg<<<cdiv((long)Mm * 32, 256), 256>>>(ei);

        k_fill<<<1, 256>>>(p_bnsum, 0.f, Hh);
        k_fill<<<1, 256>>>(p_bnsq, 0.f, Hh);
        k_bn_stats<<<cdiv(Nn, 128), 128>>>(cb[l]);
        k_bn_final<<<1, 128>>>();
        k_bn_apply<<<cdiv(NH, 256), 256>>>(cb[l], gm[l], bt[l]);
    }

    // attentional aggregation
    k_gemm<1><<<gemmN, 256>>>(p_h, A1, a1, p_tmp, Nn);     // tanh(h@A1+a1)
    k_gemm<0><<<gemmN, 256>>>(p_tmp, A2, a2, p_gate, Nn);  // gate
    k_fill<<<cdiv(Gg * Hh, 256), 256>>>(p_gmax, -FLT_MAX, Gg * Hh);
    k_fill<<<cdiv(Gg * Hh, 256), 256>>>(p_den, 0.f, Gg * Hh);
    k_fill<<<cdiv(Gg * Hh, 256), 256>>>(p_num, 0.f, Gg * Hh);
    k_pool_max<<<cdiv(NH, 256), 256>>>(batch);
    k_pool_sum<<<cdiv(NH, 256), 256>>>(batch);
    k_pool_div<<<cdiv(Gg * Hh, 256), 256>>>();

    // final linear + tanh*pi -> axis; aperture = zeros
    k_gemm<2><<<gemmG, 256>>>(p_pooled, Wf, bf, out, Gg);
    int rem = out_size - Gg * Hh;
    if (rem > 0) k_fill<<<cdiv(rem, 256), 256>>>(out + Gg * Hh, 0.f, rem);
}

// round 4
// speedup vs baseline: 1.6737x; 1.6737x over previous
#include <cuda_runtime.h>
#include <cuda_bf16.h>
#include <stdint.h>
#include <math.h>
#include <float.h>

#define Nn 50000
#define Ee 600000
#define Hh 128
#define Gg 512
#define Mm (Ee + Nn)
#define PI_F 3.14159265358979323846f

// ---------------- scratch (device globals: no allocation allowed) ----------------
static __device__ float g_loop[(size_t)Nn * Hh];
static __device__ float g_deg[Nn];
static __device__ float g_xl[(size_t)Nn * Hh];
static __device__ float g_xr[(size_t)Nn * Hh];
static __device__ float g_e[Mm];
static __device__ float g_emax[Nn];
static __device__ float g_esum[Nn];
static __device__ float g_agg[(size_t)Nn * Hh];
static __device__ float g_h[(size_t)Nn * Hh];
static __device__ float g_gate[(size_t)Nn * Hh];
static __device__ float g_tmp[(size_t)Nn * Hh];
static __device__ float g_bnsum[Hh];
static __device__ float g_bnsq[Hh];
static __device__ float g_mu[Hh];
static __device__ float g_inv[Hh];
static __device__ float g_gmax[Gg * Hh];
static __device__ float g_den[Gg * Hh];
static __device__ float g_num[Gg * Hh];
static __device__ float g_pooled[Gg * Hh];
// pre-split bf16 weight blobs in the exact smem layout: per blob
// [hi: 128n x 136k bf16 = 34816B][lo: 34816B] = 69632B, 9 blobs
#define BLOB_BYTES 69632
static __device__ __align__(16) unsigned char g_bw[9 * BLOB_BYTES];

// ---------------- mma.sync helpers (portable PTX, no tcgen05) ----------------
__device__ __forceinline__ void ldm_x4(uint32_t r[4], uint32_t addr) {
    asm volatile("ldmatrix.sync.aligned.m8n8.x4.shared.b16 {%0,%1,%2,%3}, [%4];"
                 : "=r"(r[0]), "=r"(r[1]), "=r"(r[2]), "=r"(r[3]) : "r"(addr));
}

__device__ __forceinline__ void mma16816(float* c, const uint32_t a[4], uint32_t b0, uint32_t b1) {
    asm volatile(
        "mma.sync.aligned.m16n8k16.row.col.f32.bf16.bf16.f32 "
        "{%0,%1,%2,%3}, {%4,%5,%6,%7}, {%8,%9}, {%0,%1,%2,%3};"
        : "+f"(c[0]), "+f"(c[1]), "+f"(c[2]), "+f"(c[3])
        : "r"(a[0]), "r"(a[1]), "r"(a[2]), "r"(a[3]), "r"(b0), "r"(b1));
}

// ---------------- misc helpers ----------------
__device__ __forceinline__ void atomicMaxF(float* addr, float v) {
    int* ai = reinterpret_cast<int*>(addr);
    int old = *ai;
    while (__int_as_float(old) < v) {
        int assumed = old;
        old = atomicCAS(ai, assumed, __float_as_int(v));
        if (old == assumed) break;
    }
}

__global__ void k_fill(float* __restrict__ p, float v, int n) {
    int i = blockIdx.x * blockDim.x + threadIdx.x;
    if (i < n) p[i] = v;
}

// ---------------- weight pre-split: fp32 W[128k,128n] -> blob [n][136k] hi/lo bf16 ----------------
__global__ void k_prep_B(const float* __restrict__ W, unsigned char* __restrict__ blob) {
    for (int idx = blockIdx.x * blockDim.x + threadIdx.x; idx < 16384; idx += gridDim.x * blockDim.x) {
        int n = idx >> 7;
        int k = idx & 127;
        float v = W[k * 128 + n];
        __nv_bfloat16 h = __float2bfloat16_rn(v);
        __nv_bfloat16 l = __float2bfloat16_rn(v - __bfloat162float(h));
        size_t off = ((size_t)n * 136 + k) * 2;
        *reinterpret_cast<unsigned short*>(blob + off) = *reinterpret_cast<unsigned short*>(&h);
        *reinterpret_cast<unsigned short*>(blob + 34816 + off) = *reinterpret_cast<unsigned short*>(&l);
    }
}

// ---------------- bf16x3 mma GEMM: C[rows,128] = A[rows,128] @ W[128,128] ----------------
// EPI: 0 = store +bias, 1 = store tanh(+bias), 2 = store tanh(+bias)*PI,
//      3 = GATv2 edge score (rows are edges, s/d from ei), 4 = edge score self-loop (s=d=row).
#define SM_ATT 0
#define SM_A_HI 512
#define SM_A_LO 35328
#define SM_B_HI 70144
#define SM_B_LO 104960
#define SMEM_BYTES 139776
#define ROWSTRIDE 272  // 136 bf16 * 2B

template <int EPI>
__global__ void __launch_bounds__(256, 1)
k_mma_gemm(const float* __restrict__ A, const unsigned char* __restrict__ Bblob,
           const float* __restrict__ bias, float* __restrict__ C, int rows,
           const int* __restrict__ ei, const float* __restrict__ att,
           const float* __restrict__ xl, const float* __restrict__ xr,
           float* __restrict__ e_out) {
    extern __shared__ unsigned char smem[];
    const int tid = threadIdx.x;
    const int wid = tid >> 5;
    const int lane = tid & 31;
    uint32_t sb;
    asm("{ .reg .u64 t; cvta.to.shared.u64 t, %1; cvt.u32.u64 %0, t; }" : "=r"(sb) : "l"(smem));

    const int row0 = blockIdx.x * 128;

    // copy pre-split B blob into smem (B_HI and B_LO are contiguous)
    {
        const int4* bs = reinterpret_cast<const int4*>(Bblob);
        int4* bd = reinterpret_cast<int4*>(smem + SM_B_HI);
#pragma unroll
        for (int i = 0; i < 17; i++) {
            int idx = tid + 256 * i;
            if (idx < 4352) bd[idx] = bs[idx];
        }
    }

    // load fp32 A tile, split to bf16 hi/lo, store to smem [row][136]
#pragma unroll
    for (int i = 0; i < 16; i++) {
        int idx = tid + 256 * i;
        int r = idx >> 5;
        int c4 = (idx & 31) << 2;
        int grow = row0 + r;
        float4 v = make_float4(0.f, 0.f, 0.f, 0.f);
        if (grow < rows)
            v = *reinterpret_cast<const float4*>(A + (size_t)grow * Hh + c4);
        __nv_bfloat162 h01 = __floats2bfloat162_rn(v.x, v.y);
        __nv_bfloat162 h23 = __floats2bfloat162_rn(v.z, v.w);
        __nv_bfloat162 l01 = __floats2bfloat162_rn(v.x - __low2float(h01), v.y - __high2float(h01));
        __nv_bfloat162 l23 = __floats2bfloat162_rn(v.z - __low2float(h23), v.w - __high2float(h23));
        uint32_t off = (uint32_t)r * ROWSTRIDE + c4 * 2;
        *reinterpret_cast<uint2*>(smem + SM_A_HI + off) =
            make_uint2(*reinterpret_cast<uint32_t*>(&h01), *reinterpret_cast<uint32_t*>(&h23));
        *reinterpret_cast<uint2*>(smem + SM_A_LO + off) =
            make_uint2(*reinterpret_cast<uint32_t*>(&l01), *reinterpret_cast<uint32_t*>(&l23));
    }

    if (EPI >= 3) {
        if (tid < 32)
            reinterpret_cast<float4*>(smem + SM_ATT)[tid] =
                reinterpret_cast<const float4*>(att)[tid];
    }
    __syncthreads();

    // ---- mma mainloop: warp wid owns rows m0..m0+15 of the tile, all 128 cols ----
    const int m0 = wid * 16;
    float c[64];
#pragma unroll
    for (int i = 0; i < 64; i++) c[i] = 0.f;

    // ldmatrix per-thread address components
    // A: row = m0 + (lane&7) + ((lane>>3)&1)*8, col = ks*16 + ((lane>>4)&1)*8
    uint32_t a_off = (uint32_t)(m0 + (lane & 7) + ((lane >> 3) & 1) * 8) * ROWSTRIDE
                     + ((lane >> 4) & 1) * 16;
    // B: n = np*16 + (lane&7) + ((lane>>4)&1)*8, col = ks*16 + ((lane>>3)&1)*8
    uint32_t b_off = (uint32_t)((lane & 7) + ((lane >> 4) & 1) * 8) * ROWSTRIDE
                     + ((lane >> 3) & 1) * 16;
    uint32_t aHi = sb + SM_A_HI + a_off;
    uint32_t aLo = sb + SM_A_LO + a_off;
    uint32_t bHi = sb + SM_B_HI + b_off;
    uint32_t bLo = sb + SM_B_LO + b_off;

#pragma unroll
    for (int ks = 0; ks < 8; ks++) {
        uint32_t ahi[4], alo[4];
        ldm_x4(ahi, aHi + ks * 32);
        ldm_x4(alo, aLo + ks * 32);
#pragma unroll
        for (int np = 0; np < 8; np++) {
            uint32_t bh[4], blr[4];
            ldm_x4(bh, bHi + np * (16 * ROWSTRIDE) + ks * 32);
            ldm_x4(blr, bLo + np * (16 * ROWSTRIDE) + ks * 32);
            float* c0 = c + 8 * np;
            float* c1 = c + 8 * np + 4;
            mma16816(c0, ahi, bh[0], bh[1]);
            mma16816(c1, ahi, bh[2], bh[3]);
            mma16816(c0, ahi, blr[0], blr[1]);
            mma16816(c1, ahi, blr[2], blr[3]);
            mma16816(c0, alo, bh[0], bh[1]);
            mma16816(c1, alo, bh[2], bh[3]);
        }
    }

    // ---- epilogue ----
    const int q = lane & 3;
    const int rbase = row0 + m0 + (lane >> 2);

    if (EPI <= 2) {
        int r1 = rbase, r2 = rbase + 8;
#pragma unroll
        for (int j = 0; j < 16; j++) {
            int col = j * 8 + q * 2;
            float b0 = bias[col], b1 = bias[col + 1];
            if (r1 < rows) {
                float ox = c[4 * j + 0] + b0;
                float oy = c[4 * j + 1] + b1;
                if (EPI == 1) { ox = tanhf(ox); oy = tanhf(oy); }
                if (EPI == 2) { ox = tanhf(ox) * PI_F; oy = tanhf(oy) * PI_F; }
                *reinterpret_cast<float2*>(C + (size_t)r1 * Hh + col) = make_float2(ox, oy);
            }
            if (r2 < rows) {
                float ox = c[4 * j + 2] + b0;
                float oy = c[4 * j + 3] + b1;
                if (EPI == 1) { ox = tanhf(ox); oy = tanhf(oy); }
                if (EPI == 2) { ox = tanhf(ox) * PI_F; oy = tanhf(oy) * PI_F; }
                *reinterpret_cast<float2*>(C + (size_t)r2 * Hh + col) = make_float2(ox, oy);
            }
        }
    } else {
        const float* att_s = reinterpret_cast<const float*>(smem + SM_ATT);
#pragma unroll
        for (int p = 0; p < 2; p++) {
            int row = rbase + 8 * p;
            bool valid = row < rows;
            int s = 0, dd = 0;
            if (valid) {
                if (EPI == 3) { s = ei[row]; dd = ei[Ee + row]; }
                else { s = row; dd = row; }
            }
            const float* xlp = xl + (size_t)s * Hh;
            const float* xrp = xr + (size_t)dd * Hh;
            float acc = 0.f;
            if (valid) {
#pragma unroll
                for (int j = 0; j < 16; j++) {
                    int col = j * 8 + q * 2;
                    float2 xa = *reinterpret_cast<const float2*>(xlp + col);
                    float2 xb = *reinterpret_cast<const float2*>(xrp + col);
                    float2 at = *reinterpret_cast<const float2*>(att_s + col);
                    float m;
                    m = c[4 * j + 2 * p + 0] + xa.x + xb.x;
                    m = m > 0.f ? m : 0.2f * m;
                    acc = fmaf(m, at.x, acc);
                    m = c[4 * j + 2 * p + 1] + xa.y + xb.y;
                    m = m > 0.f ? m : 0.2f * m;
                    acc = fmaf(m, at.y, acc);
                }
            }
            acc += __shfl_xor_sync(0xffffffffu, acc, 1);
            acc += __shfl_xor_sync(0xffffffffu, acc, 2);
            if (valid && q == 0) e_out[row] = acc;
        }
    }
}

// ---------------- self-loop edge_attr mean ----------------
__global__ void k_scatter_loop(const int* __restrict__ ei, const float* __restrict__ eattr) {
    int t = blockIdx.x * blockDim.x + threadIdx.x;
    int w = t >> 5, lane = t & 31;
    if (w >= Ee) return;
    int d = ei[Ee + w];
    float4 a = reinterpret_cast<const float4*>(eattr)[(size_t)w * (Hh / 4) + lane];
    float* p = g_loop + (size_t)d * Hh + lane * 4;
    atomicAdd(p + 0, a.x); atomicAdd(p + 1, a.y);
    atomicAdd(p + 2, a.z); atomicAdd(p + 3, a.w);
    if (lane == 0) atomicAdd(&g_deg[d], 1.0f);
}

__global__ void k_div_loop() {
    int i = blockIdx.x * blockDim.x + threadIdx.x;
    if (i >= Nn * Hh) return;
    g_loop[i] = g_loop[i] / fmaxf(g_deg[i >> 7], 1.0f);
}

// ---------------- GATv2 softmax + aggregation ----------------
__global__ void k_edge_max(const int* __restrict__ ei) {
    int w = blockIdx.x * blockDim.x + threadIdx.x;
    if (w >= Mm) return;
    int d = (w < Ee) ? ei[Ee + w] : (w - Ee);
    atomicMaxF(&g_emax[d], g_e[w]);
}

__global__ void k_edge_expsum(const int* __restrict__ ei) {
    int w = blockIdx.x * blockDim.x + threadIdx.x;
    if (w >= Mm) return;
    int d = (w < Ee) ? ei[Ee + w] : (w - Ee);
    float ex = expf(g_e[w] - g_emax[d]);
    g_e[w] = ex;
    atomicAdd(&g_esum[d], ex);
}

__global__ void k_edge_agg(const int* __restrict__ ei) {
    int t = blockIdx.x * blockDim.x + threadIdx.x;
    int w = t >> 5, lane = t & 31;
    if (w >= Mm) return;
    int s, d;
    if (w < Ee) { s = ei[w]; d = ei[Ee + w]; } else { s = w - Ee; d = s; }
    float alpha = g_e[w] / g_esum[d];
    float4 a = reinterpret_cast<const float4*>(g_xl)[s * 32 + lane];
    float* p = g_agg + (size_t)d * Hh + lane * 4;
    atomicAdd(p + 0, alpha * a.x); atomicAdd(p + 1, alpha * a.y);
    atomicAdd(p + 2, alpha * a.z); atomicAdd(p + 3, alpha * a.w);
}

// ---------------- batchnorm (population stats) + tanh ----------------
__global__ void k_bn_stats(const float* __restrict__ cb) {
    int j = threadIdx.x;
    int r0 = blockIdx.x * 128;
    int r1 = min(r0 + 128, Nn);
    float cbj = cb[j];
    float s = 0.f, q = 0.f;
    for (int r = r0; r < r1; r++) {
        float v = g_agg[(size_t)r * Hh + j] + cbj;
        s += v; q += v * v;
    }
    atomicAdd(&g_bnsum[j], s);
    atomicAdd(&g_bnsq[j], q);
}

__global__ void k_bn_final() {
    int j = threadIdx.x;
    float mu = g_bnsum[j] / (float)Nn;
    float var = g_bnsq[j] / (float)Nn - mu * mu;
    g_mu[j] = mu;
    g_inv[j] = rsqrtf(var + 1e-5f);
}

__global__ void k_bn_apply(const float* __restrict__ cb, const float* __restrict__ gam,
                           const float* __restrict__ bet) {
    int i = blockIdx.x * blockDim.x + threadIdx.x;
    if (i >= Nn * Hh) return;
    int j = i & 127;
    float v = g_agg[i] + cb[j];
    v = (v - g_mu[j]) * g_inv[j] * gam[j] + bet[j];
    g_h[i] = tanhf(v);
}

// ---------------- attentional pooling ----------------
__global__ void k_pool_max(const int* __restrict__ batch) {
    int i = blockIdx.x * blockDim.x + threadIdx.x;
    if (i >= Nn * Hh) return;
    int n = i >> 7, j = i & 127;
    atomicMaxF(&g_gmax[batch[n] * Hh + j], g_gate[i]);
}

__global__ void k_pool_sum(const int* __restrict__ batch) {
    int i = blockIdx.x * blockDim.x + threadIdx.x;
    if (i >= Nn * Hh) return;
    int n = i >> 7, j = i & 127;
    int gi = batch[n] * Hh + j;
    float ex = expf(g_gate[i] - g_gmax[gi]);
    atomicAdd(&g_den[gi], ex);
    atomicAdd(&g_num[gi], ex * g_h[i]);
}

__global__ void k_pool_div() {
    int i = blockIdx.x * blockDim.x + threadIdx.x;
    if (i >= Gg * Hh) return;
    g_pooled[i] = g_num[i] / fmaxf(g_den[i], 1e-16f);
}

// ---------------- launch ----------------
static inline int cdiv(long a, long b) { return (int)((a + b - 1) / b); }

extern "C" void kernel_launch(void* const* d_in, const int* in_sizes, int n_in,
                              void* d_out, int out_size) {
    const float* x     = (const float*)d_in[0];
    const int*   ei    = (const int*)d_in[1];
    const float* eattr = (const float*)d_in[2];
    const int*   batch = (const int*)d_in[3];
    const float* Wl[2]  = {(const float*)d_in[4],  (const float*)d_in[11]};
    const float* bl[2]  = {(const float*)d_in[5],  (const float*)d_in[12]};
    const float* Wr[2]  = {(const float*)d_in[6],  (const float*)d_in[13]};
    const float* br[2]  = {(const float*)d_in[7],  (const float*)d_in[14]};
    const float* We[2]  = {(const float*)d_in[8],  (const float*)d_in[15]};
    const float* att[2] = {(const float*)d_in[9],  (const float*)d_in[16]};
    const float* cb[2]  = {(const float*)d_in[10], (const float*)d_in[17]};
    const float* gm[2]  = {(const float*)d_in[18], (const float*)d_in[20]};
    const float* bt[2]  = {(const float*)d_in[19], (const float*)d_in[21]};
    const float* A1 = (const float*)d_in[22]; const float* a1 = (const float*)d_in[23];
    const float* A2 = (const float*)d_in[24]; const float* a2 = (const float*)d_in[25];
    const float* Wf = (const float*)d_in[26]; const float* bf = (const float*)d_in[27];
    float* out = (float*)d_out;

    float *p_loop, *p_xl, *p_xr, *p_e, *p_emax, *p_esum, *p_agg, *p_h,
          *p_gate, *p_tmp, *p_bnsum, *p_bnsq, *p_gmax, *p_den, *p_num, *p_pooled, *p_deg;
    unsigned char* p_bw;
    cudaGetSymbolAddress((void**)&p_loop, g_loop);
    cudaGetSymbolAddress((void**)&p_deg, g_deg);
    cudaGetSymbolAddress((void**)&p_xl, g_xl);
    cudaGetSymbolAddress((void**)&p_xr, g_xr);
    cudaGetSymbolAddress((void**)&p_e, g_e);
    cudaGetSymbolAddress((void**)&p_emax, g_emax);
    cudaGetSymbolAddress((void**)&p_esum, g_esum);
    cudaGetSymbolAddress((void**)&p_agg, g_agg);
    cudaGetSymbolAddress((void**)&p_h, g_h);
    cudaGetSymbolAddress((void**)&p_gate, g_gate);
    cudaGetSymbolAddress((void**)&p_tmp, g_tmp);
    cudaGetSymbolAddress((void**)&p_bnsum, g_bnsum);
    cudaGetSymbolAddress((void**)&p_bnsq, g_bnsq);
    cudaGetSymbolAddress((void**)&p_gmax, g_gmax);
    cudaGetSymbolAddress((void**)&p_den, g_den);
    cudaGetSymbolAddress((void**)&p_num, g_num);
    cudaGetSymbolAddress((void**)&p_pooled, g_pooled);
    cudaGetSymbolAddress((void**)&p_bw, g_bw);

    cudaFuncSetAttribute(k_mma_gemm<0>, cudaFuncAttributeMaxDynamicSharedMemorySize, SMEM_BYTES);
    cudaFuncSetAttribute(k_mma_gemm<1>, cudaFuncAttributeMaxDynamicSharedMemorySize, SMEM_BYTES);
    cudaFuncSetAttribute(k_mma_gemm<2>, cudaFuncAttributeMaxDynamicSharedMemorySize, SMEM_BYTES);
    cudaFuncSetAttribute(k_mma_gemm<3>, cudaFuncAttributeMaxDynamicSharedMemorySize, SMEM_BYTES);
    cudaFuncSetAttribute(k_mma_gemm<4>, cudaFuncAttributeMaxDynamicSharedMemorySize, SMEM_BYTES);

    const int NH = Nn * Hh;
    const int tilesN = cdiv(Nn, 128), tilesE = cdiv(Ee, 128), tilesG = cdiv(Gg, 128);

    // weight pre-split (order: Wl1,Wr1,We1,Wl2,Wr2,We2,A1,A2,Wf)
    const float* wmats[9] = {Wl[0], Wr[0], We[0], Wl[1], Wr[1], We[1], A1, A2, Wf};
    for (int i = 0; i < 9; i++)
        k_prep_B<<<32, 512>>>(wmats[i], p_bw + (size_t)i * BLOB_BYTES);

    // self-loop edge_attr = per-dst mean
    k_fill<<<cdiv(NH, 256), 256>>>(p_loop, 0.f, NH);
    k_fill<<<cdiv(Nn, 256), 256>>>(p_deg, 0.f, Nn);
    k_scatter_loop<<<cdiv((long)Ee * 32, 256), 256>>>(ei, eattr);
    k_div_loop<<<cdiv(NH, 256), 256>>>();

    for (int l = 0; l < 2; l++) {
        const float* xin = (l == 0) ? x : p_h;
        const unsigned char* bwl = p_bw + (size_t)(3 * l + 0) * BLOB_BYTES;
        const unsigned char* bwr = p_bw + (size_t)(3 * l + 1) * BLOB_BYTES;
        const unsigned char* bwe = p_bw + (size_t)(3 * l + 2) * BLOB_BYTES;

        k_mma_gemm<0><<<tilesN, 256, SMEM_BYTES>>>(xin, bwl, bl[l], p_xl, Nn,
                                                   nullptr, nullptr, nullptr, nullptr, nullptr);
        k_mma_gemm<0><<<tilesN, 256, SMEM_BYTES>>>(xin, bwr, br[l], p_xr, Nn,
                                                   nullptr, nullptr, nullptr, nullptr, nullptr);

        k_fill<<<cdiv(Nn, 256), 256>>>(p_emax, -FLT_MAX, Nn);
        k_fill<<<cdiv(Nn, 256), 256>>>(p_esum, 0.f, Nn);
        k_fill<<<cdiv(NH, 256), 256>>>(p_agg, 0.f, NH);

        // fused We-GEMM + edge score (no eW materialization)
        k_mma_gemm<3><<<tilesE, 256, SMEM_BYTES>>>(eattr, bwe, nullptr, nullptr, Ee,
                                                   ei, att[l], p_xl, p_xr, p_e);
        k_mma_gemm<4><<<tilesN, 256, SMEM_BYTES>>>(p_loop, bwe, nullptr, nullptr, Nn,
                                                   ei, att[l], p_xl, p_xr, p_e + Ee);

        k_edge_max<<<cdiv(Mm, 256), 256>>>(ei);
        k_edge_expsum<<<cdiv(Mm, 256), 256>>>(ei);
        k_edge_agg<<<cdiv((long)Mm * 32, 256), 256>>>(ei);

        k_fill<<<1, 256>>>(p_bnsum, 0.f, Hh);
        k_fill<<<1, 256>>>(p_bnsq, 0.f, Hh);
        k_bn_stats<<<cdiv(Nn, 128), 128>>>(cb[l]);
        k_bn_final<<<1, 128>>>();
        k_bn_apply<<<cdiv(NH, 256), 256>>>(cb[l], gm[l], bt[l]);
    }

    // attentional aggregation: gate = tanh(h@A1+a1)@A2 + a2
    k_mma_gemm<1><<<tilesN, 256, SMEM_BYTES>>>(p_h, p_bw + 6ul * BLOB_BYTES, a1, p_tmp, Nn,
                                               nullptr, nullptr, nullptr, nullptr, nullptr);
    k_mma_gemm<0><<<tilesN, 256, SMEM_BYTES>>>(p_tmp, p_bw + 7ul * BLOB_BYTES, a2, p_gate, Nn,
                                               nullptr, nullptr, nullptr, nullptr, nullptr);
    k_fill<<<cdiv(Gg * Hh, 256), 256>>>(p_gmax, -FLT_MAX, Gg * Hh);
    k_fill<<<cdiv(Gg * Hh, 256), 256>>>(p_den, 0.f, Gg * Hh);
    k_fill<<<cdiv(Gg * Hh, 256), 256>>>(p_num, 0.f, Gg * Hh);
    k_pool_max<<<cdiv(NH, 256), 256>>>(batch);
    k_pool_sum<<<cdiv(NH, 256), 256>>>(batch);
    k_pool_div<<<cdiv(Gg * Hh, 256), 256>>>();

    // final linear + tanh*pi -> axis; aperture = zeros
    k_mma_gemm<2><<<tilesG, 256, SMEM_BYTES>>>(p_pooled, p_bw + 8ul * BLOB_BYTES, bf, out, Gg,
                                               nullptr, nullptr, nullptr, nullptr, nullptr);
    int rem = out_size - Gg * Hh;
    if (rem > 0) k_fill<<<cdiv(rem, 256), 256>>>(out + Gg * Hh, 0.f, rem);
}

// round 5
// speedup vs baseline: 2.4277x; 1.4505x over previous
#include <cuda_runtime.h>
#include <cuda_bf16.h>
#include <stdint.h>
#include <math.h>
#include <float.h>

#define Nn 50000
#define Ee 600000
#define Hh 128
#define Gg 512
#define PI_F 3.14159265358979323846f

// ---------------- scratch (device globals: no allocation allowed) ----------------
static __device__ float g_loop[(size_t)Nn * Hh];
static __device__ float g_xl[(size_t)Nn * Hh];
static __device__ float g_xr[(size_t)Nn * Hh];
static __device__ float g_ecsr[Ee];     // edge scores in CSR order
static __device__ float g_eself[Nn];    // self-loop scores
static __device__ float g_agg[(size_t)Nn * Hh];
static __device__ float g_h[(size_t)Nn * Hh];
static __device__ float g_gate[(size_t)Nn * Hh];
static __device__ float g_tmp[(size_t)Nn * Hh];
static __device__ float g_bnsum[Hh];
static __device__ float g_bnsq[Hh];
static __device__ float g_mu[Hh];
static __device__ float g_inv[Hh];
static __device__ float g_pooled[Gg * Hh];
// CSR
static __device__ int g_rowptr[Nn + 1];
static __device__ int g_wp[Nn];
static __device__ int g_eid[Ee];   // edge id per CSR slot
static __device__ int g_srcC[Ee];  // src node per CSR slot
static __device__ int g_pos[Ee];   // CSR slot per edge id
static __device__ int g_gstart[Gg + 1];
// pre-split bf16 weight blobs in the exact smem layout: per blob
// [hi: 128n x 136k bf16 = 34816B][lo: 34816B] = 69632B, 9 blobs
#define BLOB_BYTES 69632
static __device__ __align__(16) unsigned char g_bw[9 * BLOB_BYTES];

// ---------------- mma.sync helpers (portable PTX, no tcgen05) ----------------
__device__ __forceinline__ void ldm_x4(uint32_t r[4], uint32_t addr) {
    asm volatile("ldmatrix.sync.aligned.m8n8.x4.shared.b16 {%0,%1,%2,%3}, [%4];"
                 : "=r"(r[0]), "=r"(r[1]), "=r"(r[2]), "=r"(r[3]) : "r"(addr));
}

__device__ __forceinline__ void mma16816(float* c, const uint32_t a[4], uint32_t b0, uint32_t b1) {
    asm volatile(
        "mma.sync.aligned.m16n8k16.row.col.f32.bf16.bf16.f32 "
        "{%0,%1,%2,%3}, {%4,%5,%6,%7}, {%8,%9}, {%0,%1,%2,%3};"
        : "+f"(c[0]), "+f"(c[1]), "+f"(c[2]), "+f"(c[3])
        : "r"(a[0]), "r"(a[1]), "r"(a[2]), "r"(a[3]), "r"(b0), "r"(b1));
}

__global__ void k_fill(float* __restrict__ p, float v, int n) {
    int i = blockIdx.x * blockDim.x + threadIdx.x;
    if (i < n) p[i] = v;
}

__global__ void k_ifill(int* __restrict__ p, int v, int n) {
    int i = blockIdx.x * blockDim.x + threadIdx.x;
    if (i < n) p[i] = v;
}

// ---------------- CSR build ----------------
__global__ void k_hist(const int* __restrict__ ei) {
    int e = blockIdx.x * blockDim.x + threadIdx.x;
    if (e < Ee) atomicAdd(&g_wp[ei[Ee + e]], 1);
}

__global__ void k_scan() {
    __shared__ int sh[1024];
    int tid = threadIdx.x;
    const int per = (Nn + 1023) >> 10;
    int lo = tid * per;
    int hi = min(lo + per, Nn);
    int s = 0;
    for (int i = lo; i < hi; i++) s += g_wp[i];
    sh[tid] = s;
    __syncthreads();
    for (int o = 1; o < 1024; o <<= 1) {
        int v = (tid >= o) ? sh[tid - o] : 0;
        __syncthreads();
        sh[tid] += v;
        __syncthreads();
    }
    int off = sh[tid] - s;  // exclusive prefix
    for (int i = lo; i < hi; i++) {
        int c = g_wp[i];
        g_rowptr[i] = off;
        g_wp[i] = off;
        off += c;
    }
    if (tid == 1023) g_rowptr[Nn] = Ee;
}

__global__ void k_place(const int* __restrict__ ei) {
    int e = blockIdx.x * blockDim.x + threadIdx.x;
    if (e >= Ee) return;
    int d = ei[Ee + e];
    int p = atomicAdd(&g_wp[d], 1);
    g_pos[e] = p;
    g_eid[p] = e;
    g_srcC[p] = ei[e];
}

// ---------------- loop_attr: per-dst mean of incident edge_attr (CSR gather) ----------------
__global__ void k_loop_mean(const float* __restrict__ eattr) {
    int t = blockIdx.x * blockDim.x + threadIdx.x;
    int d = t >> 5, lane = t & 31;
    if (d >= Nn) return;
    int start = g_rowptr[d], end = g_rowptr[d + 1];
    float4 acc = make_float4(0.f, 0.f, 0.f, 0.f);
    for (int j = start; j < end; j++) {
        int eid = g_eid[j];
        float4 a = reinterpret_cast<const float4*>(eattr)[(size_t)eid * 32 + lane];
        acc.x += a.x; acc.y += a.y; acc.z += a.z; acc.w += a.w;
    }
    float inv = 1.f / (float)max(end - start, 1);
    reinterpret_cast<float4*>(g_loop)[(size_t)d * 32 + lane] =
        make_float4(acc.x * inv, acc.y * inv, acc.z * inv, acc.w * inv);
}

// ---------------- per-dst softmax + aggregation (warp per node, no atomics) ----------------
__global__ void k_node_agg() {
    int t = blockIdx.x * blockDim.x + threadIdx.x;
    int d = t >> 5, lane = t & 31;
    if (d >= Nn) return;
    int start = g_rowptr[d], end = g_rowptr[d + 1];

    float es = g_eself[d];
    // pass 1: max
    float m = es;
    for (int j = start + lane; j < end; j += 32) m = fmaxf(m, g_ecsr[j]);
#pragma unroll
    for (int o = 16; o > 0; o >>= 1) m = fmaxf(m, __shfl_xor_sync(0xffffffffu, m, o));
    // pass 2: expsum
    float s = (lane == 0) ? expf(es - m) : 0.f;
    for (int j = start + lane; j < end; j += 32) s += expf(g_ecsr[j] - m);
#pragma unroll
    for (int o = 16; o > 0; o >>= 1) s += __shfl_xor_sync(0xffffffffu, s, o);
    float inv = 1.f / s;
    // pass 3: weighted gather
    float aS = expf(es - m) * inv;
    float4 xv = reinterpret_cast<const float4*>(g_xl)[(size_t)d * 32 + lane];
    float4 acc = make_float4(aS * xv.x, aS * xv.y, aS * xv.z, aS * xv.w);
    for (int j = start; j < end; j++) {
        float a = expf(g_ecsr[j] - m) * inv;
        int sn = g_srcC[j];
        float4 v = reinterpret_cast<const float4*>(g_xl)[(size_t)sn * 32 + lane];
        acc.x = fmaf(a, v.x, acc.x); acc.y = fmaf(a, v.y, acc.y);
        acc.z = fmaf(a, v.z, acc.z); acc.w = fmaf(a, v.w, acc.w);
    }
    reinterpret_cast<float4*>(g_agg)[(size_t)d * 32 + lane] = acc;
}

// ---------------- bf16x3 mma GEMM: C[rows,128] = A[rows,128] @ W[128,128] ----------------
// EPI: 0 = store +bias, 1 = store tanh(+bias), 2 = store tanh(+bias)*PI,
//      3 = GATv2 edge score -> e_out[pos[row]], 4 = edge score self-loop (s=d=row) -> e_out[row].
#define SM_ATT 0
#define SM_A_HI 512
#define SM_A_LO 35328
#define SM_B_HI 70144
#define SM_B_LO 104960
#define SMEM_BYTES 139776
#define ROWSTRIDE 272  // 136 bf16 * 2B

template <int EPI>
__global__ void __launch_bounds__(256, 1)
k_mma_gemm(const float* __restrict__ A, const unsigned char* __restrict__ Bblob,
           const float* __restrict__ bias, float* __restrict__ C, int rows,
           const int* __restrict__ ei, const float* __restrict__ att,
           const float* __restrict__ xl, const float* __restrict__ xr,
           float* __restrict__ e_out, const int* __restrict__ pos) {
    extern __shared__ unsigned char smem[];
    const int tid = threadIdx.x;
    const int wid = tid >> 5;
    const int lane = tid & 31;
    uint32_t sb;
    asm("{ .reg .u64 t; cvta.to.shared.u64 t, %1; cvt.u32.u64 %0, t; }" : "=r"(sb) : "l"(smem));

    const int row0 = blockIdx.x * 128;

    // copy pre-split B blob into smem (B_HI and B_LO are contiguous)
    {
        const int4* bs = reinterpret_cast<const int4*>(Bblob);
        int4* bd = reinterpret_cast<int4*>(smem + SM_B_HI);
#pragma unroll
        for (int i = 0; i < 17; i++) {
            int idx = tid + 256 * i;
            if (idx < 4352) bd[idx] = bs[idx];
        }
    }

    // load fp32 A tile, split to bf16 hi/lo, store to smem [row][136]
#pragma unroll
    for (int i = 0; i < 16; i++) {
        int idx = tid + 256 * i;
        int r = idx >> 5;
        int c4 = (idx & 31) << 2;
        int grow = row0 + r;
        float4 v = make_float4(0.f, 0.f, 0.f, 0.f);
        if (grow < rows)
            v = *reinterpret_cast<const float4*>(A + (size_t)grow * Hh + c4);
        __nv_bfloat162 h01 = __floats2bfloat162_rn(v.x, v.y);
        __nv_bfloat162 h23 = __floats2bfloat162_rn(v.z, v.w);
        __nv_bfloat162 l01 = __floats2bfloat162_rn(v.x - __low2float(h01), v.y - __high2float(h01));
        __nv_bfloat162 l23 = __floats2bfloat162_rn(v.z - __low2float(h23), v.w - __high2float(h23));
        uint32_t off = (uint32_t)r * ROWSTRIDE + c4 * 2;
        *reinterpret_cast<uint2*>(smem + SM_A_HI + off) =
            make_uint2(*reinterpret_cast<uint32_t*>(&h01), *reinterpret_cast<uint32_t*>(&h23));
        *reinterpret_cast<uint2*>(smem + SM_A_LO + off) =
            make_uint2(*reinterpret_cast<uint32_t*>(&l01), *reinterpret_cast<uint32_t*>(&l23));
    }

    if (EPI >= 3) {
        if (tid < 32)
            reinterpret_cast<float4*>(smem + SM_ATT)[tid] =
                reinterpret_cast<const float4*>(att)[tid];
    }
    __syncthreads();

    // ---- mma mainloop: warp wid owns rows m0..m0+15 of the tile, all 128 cols ----
    const int m0 = wid * 16;
    float c[64];
#pragma unroll
    for (int i = 0; i < 64; i++) c[i] = 0.f;

    uint32_t a_off = (uint32_t)(m0 + (lane & 7) + ((lane >> 3) & 1) * 8) * ROWSTRIDE
                     + ((lane >> 4) & 1) * 16;
    uint32_t b_off = (uint32_t)((lane & 7) + ((lane >> 4) & 1) * 8) * ROWSTRIDE
                     + ((lane >> 3) & 1) * 16;
    uint32_t aHi = sb + SM_A_HI + a_off;
    uint32_t aLo = sb + SM_A_LO + a_off;
    uint32_t bHi = sb + SM_B_HI + b_off;
    uint32_t bLo = sb + SM_B_LO + b_off;

#pragma unroll
    for (int ks = 0; ks < 8; ks++) {
        uint32_t ahi[4], alo[4];
        ldm_x4(ahi, aHi + ks * 32);
        ldm_x4(alo, aLo + ks * 32);
#pragma unroll
        for (int np = 0; np < 8; np++) {
            uint32_t bh[4], blr[4];
            ldm_x4(bh, bHi + np * (16 * ROWSTRIDE) + ks * 32);
            ldm_x4(blr, bLo + np * (16 * ROWSTRIDE) + ks * 32);
            float* c0 = c + 8 * np;
            float* c1 = c + 8 * np + 4;
            mma16816(c0, ahi, bh[0], bh[1]);
            mma16816(c1, ahi, bh[2], bh[3]);
            mma16816(c0, ahi, blr[0], blr[1]);
            mma16816(c1, ahi, blr[2], blr[3]);
            mma16816(c0, alo, bh[0], bh[1]);
            mma16816(c1, alo, bh[2], bh[3]);
        }
    }

    // ---- epilogue ----
    const int q = lane & 3;
    const int rbase = row0 + m0 + (lane >> 2);

    if (EPI <= 2) {
        int r1 = rbase, r2 = rbase + 8;
#pragma unroll
        for (int j = 0; j < 16; j++) {
            int col = j * 8 + q * 2;
            float b0 = bias[col], b1 = bias[col + 1];
            if (r1 < rows) {
                float ox = c[4 * j + 0] + b0;
                float oy = c[4 * j + 1] + b1;
                if (EPI == 1) { ox = tanhf(ox); oy = tanhf(oy); }
                if (EPI == 2) { ox = tanhf(ox) * PI_F; oy = tanhf(oy) * PI_F; }
                *reinterpret_cast<float2*>(C + (size_t)r1 * Hh + col) = make_float2(ox, oy);
            }
            if (r2 < rows) {
                float ox = c[4 * j + 2] + b0;
                float oy = c[4 * j + 3] + b1;
                if (EPI == 1) { ox = tanhf(ox); oy = tanhf(oy); }
                if (EPI == 2) { ox = tanhf(ox) * PI_F; oy = tanhf(oy) * PI_F; }
                *reinterpret_cast<float2*>(C + (size_t)r2 * Hh + col) = make_float2(ox, oy);
            }
        }
    } else {
        const float* att_s = reinterpret_cast<const float*>(smem + SM_ATT);
#pragma unroll
        for (int p = 0; p < 2; p++) {
            int row = rbase + 8 * p;
            bool valid = row < rows;
            int s = 0, dd = 0;
            if (valid) {
                if (EPI == 3) { s = ei[row]; dd = ei[Ee + row]; }
                else { s = row; dd = row; }
            }
            const float* xlp = xl + (size_t)s * Hh;
            const float* xrp = xr + (size_t)dd * Hh;
            float acc = 0.f;
            if (valid) {
#pragma unroll
                for (int j = 0; j < 16; j++) {
                    int col = j * 8 + q * 2;
                    float2 xa = *reinterpret_cast<const float2*>(xlp + col);
                    float2 xb = *reinterpret_cast<const float2*>(xrp + col);
                    float2 at = *reinterpret_cast<const float2*>(att_s + col);
                    float m;
                    m = c[4 * j + 2 * p + 0] + xa.x + xb.x;
                    m = m > 0.f ? m : 0.2f * m;
                    acc = fmaf(m, at.x, acc);
                    m = c[4 * j + 2 * p + 1] + xa.y + xb.y;
                    m = m > 0.f ? m : 0.2f * m;
                    acc = fmaf(m, at.y, acc);
                }
            }
            acc += __shfl_xor_sync(0xffffffffu, acc, 1);
            acc += __shfl_xor_sync(0xffffffffu, acc, 2);
            if (valid && q == 0) {
                if (EPI == 3) e_out[pos[row]] = acc;
                else e_out[row] = acc;
            }
        }
    }
}

// ---------------- weight pre-split: fp32 W[128k,128n] -> blob [n][136k] hi/lo bf16 ----------------
__global__ void k_prep_B(const float* __restrict__ W, unsigned char* __restrict__ blob) {
    for (int idx = blockIdx.x * blockDim.x + threadIdx.x; idx < 16384; idx += gridDim.x * blockDim.x) {
        int n = idx >> 7;
        int k = idx & 127;
        float v = W[k * 128 + n];
        __nv_bfloat16 h = __float2bfloat16_rn(v);
        __nv_bfloat16 l = __float2bfloat16_rn(v - __bfloat162float(h));
        size_t off = ((size_t)n * 136 + k) * 2;
        *reinterpret_cast<unsigned short*>(blob + off) = *reinterpret_cast<unsigned short*>(&h);
        *reinterpret_cast<unsigned short*>(blob + 34816 + off) = *reinterpret_cast<unsigned short*>(&l);
    }
}

// ---------------- batchnorm (population stats) + tanh ----------------
__global__ void k_bn_stats(const float* __restrict__ cb) {
    int j = threadIdx.x;
    int r0 = blockIdx.x * 128;
    int r1 = min(r0 + 128, Nn);
    float cbj = cb[j];
    float s = 0.f, q = 0.f;
    for (int r = r0; r < r1; r++) {
        float v = g_agg[(size_t)r * Hh + j] + cbj;
        s += v; q += v * v;
    }
    atomicAdd(&g_bnsum[j], s);
    atomicAdd(&g_bnsq[j], q);
}

__global__ void k_bn_final() {
    int j = threadIdx.x;
    float mu = g_bnsum[j] / (float)Nn;
    float var = g_bnsq[j] / (float)Nn - mu * mu;
    g_mu[j] = mu;
    g_inv[j] = rsqrtf(var + 1e-5f);
}

__global__ void k_bn_apply(const float* __restrict__ cb, const float* __restrict__ gam,
                           const float* __restrict__ bet) {
    int i = blockIdx.x * blockDim.x + threadIdx.x;
    if (i >= Nn * Hh) return;
    int j = i & 127;
    float v = g_agg[i] + cb[j];
    v = (v - g_mu[j]) * g_inv[j] * gam[j] + bet[j];
    g_h[i] = tanhf(v);
}

// ---------------- attentional pooling over sorted batch segments ----------------
__global__ void k_gb_min(const int* __restrict__ batch) {
    int n = blockIdx.x * blockDim.x + threadIdx.x;
    if (n < Nn) atomicMin(&g_gstart[batch[n]], n);
}

__global__ void k_gb_fix() {
    if (threadIdx.x == 0 && blockIdx.x == 0) {
        g_gstart[Gg] = Nn;
        for (int g = Gg - 1; g >= 0; g--)
            g_gstart[g] = min(g_gstart[g], g_gstart[g + 1]);
    }
}

__global__ void k_pool() {
    int g = blockIdx.x;
    int j = threadIdx.x;
    int s = g_gstart[g], e2 = g_gstart[g + 1];
    float m = -FLT_MAX;
    for (int n = s; n < e2; n++) m = fmaxf(m, g_gate[(size_t)n * Hh + j]);
    float den = 0.f, num = 0.f;
    for (int n = s; n < e2; n++) {
        float ex = expf(g_gate[(size_t)n * Hh + j] - m);
        den += ex;
        num = fmaf(ex, g_h[(size_t)n * Hh + j], num);
    }
    g_pooled[g * Hh + j] = num / fmaxf(den, 1e-16f);
}

// ---------------- launch ----------------
static inline int cdiv(long a, long b) { return (int)((a + b - 1) / b); }

extern "C" void kernel_launch(void* const* d_in, const int* in_sizes, int n_in,
                              void* d_out, int out_size) {
    const float* x     = (const float*)d_in[0];
    const int*   ei    = (const int*)d_in[1];
    const float* eattr = (const float*)d_in[2];
    const int*   batch = (const int*)d_in[3];
    const float* Wl[2]  = {(const float*)d_in[4],  (const float*)d_in[11]};
    const float* bl[2]  = {(const float*)d_in[5],  (const float*)d_in[12]};
    const float* Wr[2]  = {(const float*)d_in[6],  (const float*)d_in[13]};
    const float* br[2]  = {(const float*)d_in[7],  (const float*)d_in[14]};
    const float* We[2]  = {(const float*)d_in[8],  (const float*)d_in[15]};
    const float* att[2] = {(const float*)d_in[9],  (const float*)d_in[16]};
    const float* cb[2]  = {(const float*)d_in[10], (const float*)d_in[17]};
    const float* gm[2]  = {(const float*)d_in[18], (const float*)d_in[20]};
    const float* bt[2]  = {(const float*)d_in[19], (const float*)d_in[21]};
    const float* A1 = (const float*)d_in[22]; const float* a1 = (const float*)d_in[23];
    const float* A2 = (const float*)d_in[24]; const float* a2 = (const float*)d_in[25];
    const float* Wf = (const float*)d_in[26]; const float* bf = (const float*)d_in[27];
    float* out = (float*)d_out;

    float *p_loop, *p_xl, *p_xr, *p_ecsr, *p_eself, *p_h, *p_gate, *p_tmp,
          *p_bnsum, *p_bnsq, *p_pooled;
    int *p_wp, *p_gstart, *p_pos;
    unsigned char* p_bw;
    cudaGetSymbolAddress((void**)&p_loop, g_loop);
    cudaGetSymbolAddress((void**)&p_xl, g_xl);
    cudaGetSymbolAddress((void**)&p_xr, g_xr);
    cudaGetSymbolAddress((void**)&p_ecsr, g_ecsr);
    cudaGetSymbolAddress((void**)&p_eself, g_eself);
    cudaGetSymbolAddress((void**)&p_h, g_h);
    cudaGetSymbolAddress((void**)&p_gate, g_gate);
    cudaGetSymbolAddress((void**)&p_tmp, g_tmp);
    cudaGetSymbolAddress((void**)&p_bnsum, g_bnsum);
    cudaGetSymbolAddress((void**)&p_bnsq, g_bnsq);
    cudaGetSymbolAddress((void**)&p_pooled, g_pooled);
    cudaGetSymbolAddress((void**)&p_wp, g_wp);
    cudaGetSymbolAddress((void**)&p_gstart, g_gstart);
    cudaGetSymbolAddress((void**)&p_pos, g_pos);
    cudaGetSymbolAddress((void**)&p_bw, g_bw);

    cudaFuncSetAttribute(k_mma_gemm<0>, cudaFuncAttributeMaxDynamicSharedMemorySize, SMEM_BYTES);
    cudaFuncSetAttribute(k_mma_gemm<1>, cudaFuncAttributeMaxDynamicSharedMemorySize, SMEM_BYTES);
    cudaFuncSetAttribute(k_mma_gemm<2>, cudaFuncAttributeMaxDynamicSharedMemorySize, SMEM_BYTES);
    cudaFuncSetAttribute(k_mma_gemm<3>, cudaFuncAttributeMaxDynamicSharedMemorySize, SMEM_BYTES);
    cudaFuncSetAttribute(k_mma_gemm<4>, cudaFuncAttributeMaxDynamicSharedMemorySize, SMEM_BYTES);

    const int NH = Nn * Hh;
    const int tilesN = cdiv(Nn, 128), tilesE = cdiv(Ee, 128), tilesG = cdiv(Gg, 128);

    // weight pre-split (order: Wl1,Wr1,We1,Wl2,Wr2,We2,A1,A2,Wf)
    const float* wmats[9] = {Wl[0], Wr[0], We[0], Wl[1], Wr[1], We[1], A1, A2, Wf};
    for (int i = 0; i < 9; i++)
        k_prep_B<<<32, 512>>>(wmats[i], p_bw + (size_t)i * BLOB_BYTES);

    // ---- CSR build (once) ----
    k_ifill<<<cdiv(Nn, 256), 256>>>(p_wp, 0, Nn);
    k_hist<<<cdiv(Ee, 256), 256>>>(ei);
    k_scan<<<1, 1024>>>();
    k_place<<<cdiv(Ee, 256), 256>>>(ei);

    // graph segment bounds (once)
    k_ifill<<<cdiv(Gg + 1, 256), 256>>>(p_gstart, Nn, Gg + 1);
    k_gb_min<<<cdiv(Nn, 256), 256>>>(batch);
    k_gb_fix<<<1, 32>>>();

    // loop_attr = per-dst mean of edge_attr
    k_loop_mean<<<cdiv((long)Nn * 32, 256), 256>>>(eattr);

    for (int l = 0; l < 2; l++) {
        const float* xin = (l == 0) ? x : p_h;
        const unsigned char* bwl = p_bw + (size_t)(3 * l + 0) * BLOB_BYTES;
        const unsigned char* bwr = p_bw + (size_t)(3 * l + 1) * BLOB_BYTES;
        const unsigned char* bwe = p_bw + (size_t)(3 * l + 2) * BLOB_BYTES;

        k_mma_gemm<0><<<tilesN, 256, SMEM_BYTES>>>(xin, bwl, bl[l], p_xl, Nn,
                                                   nullptr, nullptr, nullptr, nullptr, nullptr, nullptr);
        k_mma_gemm<0><<<tilesN, 256, SMEM_BYTES>>>(xin, bwr, br[l], p_xr, Nn,
                                                   nullptr, nullptr, nullptr, nullptr, nullptr, nullptr);

        // fused We-GEMM + edge score (writes directly in CSR order via pos)
        k_mma_gemm<3><<<tilesE, 256, SMEM_BYTES>>>(eattr, bwe, nullptr, nullptr, Ee,
                                                   ei, att[l], p_xl, p_xr, p_ecsr, p_pos);
        k_mma_gemm<4><<<tilesN, 256, SMEM_BYTES>>>(p_loop, bwe, nullptr, nullptr, Nn,
                                                   ei, att[l], p_xl, p_xr, p_eself, nullptr);

        // per-dst softmax + aggregation (no atomics)
        k_node_agg<<<cdiv((long)Nn * 32, 256), 256>>>();

        k_fill<<<1, 256>>>(p_bnsum, 0.f, Hh);
        k_fill<<<1, 256>>>(p_bnsq, 0.f, Hh);
        k_bn_stats<<<cdiv(Nn, 128), 128>>>(cb[l]);
        k_bn_final<<<1, 128>>>();
        k_bn_apply<<<cdiv(NH, 256), 256>>>(cb[l], gm[l], bt[l]);
    }

    // attentional aggregation: gate = tanh(h@A1+a1)@A2 + a2
    k_mma_gemm<1><<<tilesN, 256, SMEM_BYTES>>>(p_h, p_bw + 6ul * BLOB_BYTES, a1, p_tmp, Nn,
                                               nullptr, nullptr, nullptr, nullptr, nullptr, nullptr);
    k_mma_gemm<0><<<tilesN, 256, SMEM_BYTES>>>(p_tmp, p_bw + 7ul * BLOB_BYTES, a2, p_gate, Nn,
                                               nullptr, nullptr, nullptr, nullptr, nullptr, nullptr);
    k_pool<<<Gg, 128>>>();

    // final linear + tanh*pi -> axis; aperture = zeros
    k_mma_gemm<2><<<tilesG, 256, SMEM_BYTES>>>(p_pooled, p_bw + 8ul * BLOB_BYTES, bf, out, Gg,
                                               nullptr, nullptr, nullptr, nullptr, nullptr, nullptr);
    int rem = out_size - Gg * Hh;
    if (rem > 0) k_fill<<<cdiv(rem, 256), 256>>>(out + Gg * Hh, 0.f, rem);
}